// round 5
// baseline (speedup 1.0000x reference)
#include <cuda_runtime.h>

// LSTM: B=1024, T=2048, H=32, I=1.
// One warp runs TWO independent batch sequences interleaved (ILP hides the
// per-step serial chain). Lane j owns hidden unit j. Weights shared across
// both sequences -> no extra weight registers. Gates packed (i,f),(g,o) in
// f32x2; h broadcast via duplicated smem pairs (double-buffered, converged
// warp -> no syncs). sigmoid(a)=0.5*tanh(a/2)+0.5 with pre-scaled weights.

#define B_ 1024
#define T_ 2048
#define H_ 32

typedef unsigned long long u64;

static __device__ __forceinline__ u64 pk2(float lo, float hi) {
    u64 r;
    asm("mov.b64 %0, {%1, %2};" : "=l"(r) : "f"(lo), "f"(hi));
    return r;
}
static __device__ __forceinline__ void upk2(u64 v, float& lo, float& hi) {
    asm("mov.b64 {%0, %1}, %2;" : "=f"(lo), "=f"(hi) : "l"(v));
}
static __device__ __forceinline__ u64 fma2(u64 a, u64 b, u64 c) {
    u64 d;
    asm("fma.rn.f32x2 %0, %1, %2, %3;" : "=l"(d) : "l"(a), "l"(b), "l"(c));
    return d;
}
static __device__ __forceinline__ u64 add2(u64 a, u64 b) {
    u64 d;
    asm("add.rn.f32x2 %0, %1, %2;" : "=l"(d) : "l"(a), "l"(b));
    return d;
}
static __device__ __forceinline__ float tanhf_(float x) {
    float r; asm("tanh.approx.f32 %0, %1;" : "=f"(r) : "f"(x)); return r;
}
static __device__ __forceinline__ void lds2(u64& p0, u64& p1, unsigned addr) {
    asm volatile("ld.shared.v2.b64 {%0, %1}, [%2];"
                 : "=l"(p0), "=l"(p1) : "r"(addr));
}
static __device__ __forceinline__ void sts64(unsigned addr, u64 v) {
    asm volatile("st.shared.b64 [%0], %1;" :: "r"(addr), "l"(v));
}

__global__ void __launch_bounds__(32)
lstm_kernel(const float* __restrict__ x,
            const float* __restrict__ W_ih,
            const float* __restrict__ W_hh,
            const float* __restrict__ b_ih,
            const float* __restrict__ b_hh,
            const float* __restrict__ W_out,
            const float* __restrict__ b_out,
            float* __restrict__ out) {
    const int j  = threadIdx.x;        // hidden unit
    const int bA = blockIdx.x * 2;     // first batch element
    const int bB = bA + 1;             // second batch element

    __shared__ u64 hA[2][H_];          // duplicated (h,h) pairs, double-buffered
    __shared__ u64 hB[2][H_];
    __shared__ float pbufA[32][33];    // per-step output partials (padded)
    __shared__ float pbufB[32][33];
    volatile float (*pvA)[33] = (volatile float (*)[33])pbufA;
    volatile float (*pvB)[33] = (volatile float (*)[33])pbufB;

    const float sI = 0.5f, sF = 0.5f, sG = 1.0f, sO = 0.5f;

    // Pre-scaled packed recurrent weights (shared by both sequences).
    u64 wif[H_], wgo[H_];
#pragma unroll
    for (int k = 0; k < H_; k++) {
        wif[k] = pk2(sI * W_hh[(0 * H_ + j) * H_ + k],
                     sF * W_hh[(1 * H_ + j) * H_ + k]);
        wgo[k] = pk2(sG * W_hh[(2 * H_ + j) * H_ + k],
                     sO * W_hh[(3 * H_ + j) * H_ + k]);
    }
    const u64 wih_if = pk2(sI * W_ih[0 * H_ + j], sF * W_ih[1 * H_ + j]);
    const u64 wih_go = pk2(sG * W_ih[2 * H_ + j], sO * W_ih[3 * H_ + j]);
    const u64 bs_if  = pk2(sI * (b_ih[0 * H_ + j] + b_hh[0 * H_ + j]),
                           sF * (b_ih[1 * H_ + j] + b_hh[1 * H_ + j]));
    const u64 bs_go  = pk2(sG * (b_ih[2 * H_ + j] + b_hh[2 * H_ + j]),
                           sO * (b_ih[3 * H_ + j] + b_hh[3 * H_ + j]));
    const float wout = W_out[j];
    const float bout = b_out[0];
    const u64 z2 = 0ull;

    const unsigned hA0 = (unsigned)__cvta_generic_to_shared(&hA[0][0]);
    const unsigned hA1 = hA0 + (unsigned)(H_ * sizeof(u64));
    const unsigned hB0 = (unsigned)__cvta_generic_to_shared(&hB[0][0]);
    const unsigned hB1 = hB0 + (unsigned)(H_ * sizeof(u64));

    float cA = 0.0f, cB = 0.0f;
    sts64(hA0 + j * 8, z2);
    sts64(hB0 + j * 8, z2);

    const float* xbA = x + (size_t)bA * T_;
    const float* xbB = x + (size_t)bB * T_;
    float* obA = out + (size_t)bA * T_;
    float* obB = out + (size_t)bB * T_;
    float xcA = xbA[0], xcB = xbB[0];

    for (int t0 = 0; t0 < T_; t0 += 32) {
#pragma unroll 2
        for (int tt = 0; tt < 32; ++tt) {
            const int t = t0 + tt;
            const int tn = (t + 1 < T_) ? (t + 1) : (T_ - 1);
            const float xnA = xbA[tn];
            const float xnB = xbB[tn];

            const unsigned rdA = (t & 1) ? hA1 : hA0;
            const unsigned wrA = ((t & 1) ? hA0 : hA1) + j * 8;
            const unsigned rdB = (t & 1) ? hB1 : hB0;
            const unsigned wrB = ((t & 1) ? hB0 : hB1) + j * 8;

            const u64 xdA = pk2(xcA, xcA);
            const u64 xdB = pk2(xcB, xcB);

            u64 aA0 = fma2(xdA, wih_if, bs_if), gA0 = fma2(xdA, wih_go, bs_go);
            u64 aB0 = fma2(xdB, wih_if, bs_if), gB0 = fma2(xdB, wih_go, bs_go);
            u64 aA1 = z2, gA1 = z2, aB1 = z2, gB1 = z2;

#pragma unroll
            for (int k = 0; k < H_; k += 2) {
                u64 pA0, pA1, pB0, pB1;
                lds2(pA0, pA1, rdA + k * 8);
                lds2(pB0, pB1, rdB + k * 8);
                aA0 = fma2(pA0, wif[k],     aA0);
                aB0 = fma2(pB0, wif[k],     aB0);
                gA0 = fma2(pA0, wgo[k],     gA0);
                gB0 = fma2(pB0, wgo[k],     gB0);
                aA1 = fma2(pA1, wif[k + 1], aA1);
                aB1 = fma2(pB1, wif[k + 1], aB1);
                gA1 = fma2(pA1, wgo[k + 1], gA1);
                gB1 = fma2(pB1, wgo[k + 1], gB1);
            }
            const u64 aifA = add2(aA0, aA1), agoA = add2(gA0, gA1);
            const u64 aifB = add2(aB0, aB1), agoB = add2(gB0, gB1);

            float aiA, afA, agA, aoA, aiB, afB, agB, aoB;
            upk2(aifA, aiA, afA);
            upk2(aifB, aiB, afB);
            upk2(agoA, agA, aoA);
            upk2(agoB, agB, aoB);

            const float tiA = tanhf_(aiA), tiB = tanhf_(aiB);
            const float tfA = tanhf_(afA), tfB = tanhf_(afB);
            const float g_A = tanhf_(agA), g_B = tanhf_(agB);
            const float toA = tanhf_(aoA), toB = tanhf_(aoB);

            const float i_A = fmaf(tiA, 0.5f, 0.5f), i_B = fmaf(tiB, 0.5f, 0.5f);
            const float f_A = fmaf(tfA, 0.5f, 0.5f), f_B = fmaf(tfB, 0.5f, 0.5f);
            const float o_A = fmaf(toA, 0.5f, 0.5f), o_B = fmaf(toB, 0.5f, 0.5f);

            cA = fmaf(f_A, cA, i_A * g_A);
            cB = fmaf(f_B, cB, i_B * g_B);
            const float hAv = o_A * tanhf_(cA);
            const float hBv = o_B * tanhf_(cB);

            sts64(wrA, pk2(hAv, hAv));
            sts64(wrB, pk2(hBv, hBv));
            pvA[tt][j] = hAv * wout;
            pvB[tt][j] = hBv * wout;
            xcA = xnA;
            xcB = xnB;
        }
        // Transposed reductions: lane j sums the 32 partials of timestep t0+j.
        float sA0 = 0.0f, sA1 = 0.0f, sB0 = 0.0f, sB1 = 0.0f;
#pragma unroll
        for (int k = 0; k < 32; k += 2) {
            sA0 += pvA[j][k];
            sB0 += pvB[j][k];
            sA1 += pvA[j][k + 1];
            sB1 += pvB[j][k + 1];
        }
        obA[t0 + j] = sA0 + sA1 + bout;
        obB[t0 + j] = sB0 + sB1 + bout;
    }
}

extern "C" void kernel_launch(void* const* d_in, const int* in_sizes, int n_in,
                              void* d_out, int out_size) {
    const float* x     = (const float*)d_in[0];
    const float* W_ih  = (const float*)d_in[1];
    const float* W_hh  = (const float*)d_in[2];
    const float* b_ih  = (const float*)d_in[3];
    const float* b_hh  = (const float*)d_in[4];
    const float* W_out = (const float*)d_in[5];
    const float* b_out = (const float*)d_in[6];
    float* out = (float*)d_out;

    lstm_kernel<<<B_ / 2, 32>>>(x, W_ih, W_hh, b_ih, b_hh, W_out, b_out, out);
}

// round 6
// speedup vs baseline: 1.0512x; 1.0512x over previous
#include <cuda_runtime.h>

// LSTM: B=1024, T=2048, H=32, I=1.
// One warp runs TWO sequences with a HALF-STEP SKEW:
//   ... gatesB(t) || tailA(t), gatesA(t+1) || tailB(t) ...
// so every serial tail (tanh ladder, c/h update, STS->LDS) is covered by the
// other sequence's 64 independent FMA2s. Lane j owns hidden unit j.
// Gates packed (i,f),(g,o) in f32x2. sigmoid(a)=0.5*tanh(a/2)+0.5, pre-scaled.

#define B_ 1024
#define T_ 2048
#define H_ 32

typedef unsigned long long u64;

static __device__ __forceinline__ u64 pk2(float lo, float hi) {
    u64 r;
    asm("mov.b64 %0, {%1, %2};" : "=l"(r) : "f"(lo), "f"(hi));
    return r;
}
static __device__ __forceinline__ void upk2(u64 v, float& lo, float& hi) {
    asm("mov.b64 {%0, %1}, %2;" : "=f"(lo), "=f"(hi) : "l"(v));
}
static __device__ __forceinline__ u64 fma2(u64 a, u64 b, u64 c) {
    u64 d;
    asm("fma.rn.f32x2 %0, %1, %2, %3;" : "=l"(d) : "l"(a), "l"(b), "l"(c));
    return d;
}
static __device__ __forceinline__ u64 add2(u64 a, u64 b) {
    u64 d;
    asm("add.rn.f32x2 %0, %1, %2;" : "=l"(d) : "l"(a), "l"(b));
    return d;
}
static __device__ __forceinline__ float tanhf_(float x) {
    float r; asm("tanh.approx.f32 %0, %1;" : "=f"(r) : "f"(x)); return r;
}
static __device__ __forceinline__ void lds2(u64& p0, u64& p1, unsigned addr) {
    asm volatile("ld.shared.v2.b64 {%0, %1}, [%2];"
                 : "=l"(p0), "=l"(p1) : "r"(addr));
}
static __device__ __forceinline__ void sts64(unsigned addr, u64 v) {
    asm volatile("st.shared.b64 [%0], %1;" :: "r"(addr), "l"(v));
}

__global__ void __launch_bounds__(32)
lstm_kernel(const float* __restrict__ x,
            const float* __restrict__ W_ih,
            const float* __restrict__ W_hh,
            const float* __restrict__ b_ih,
            const float* __restrict__ b_hh,
            const float* __restrict__ W_out,
            const float* __restrict__ b_out,
            float* __restrict__ out) {
    const int j  = threadIdx.x;
    const int bA = blockIdx.x * 2;
    const int bB = bA + 1;

    __shared__ u64 hA[2][H_];
    __shared__ u64 hB[2][H_];
    __shared__ float pbufA[32][33];
    __shared__ float pbufB[32][33];
    volatile float (*pvA)[33] = (volatile float (*)[33])pbufA;
    volatile float (*pvB)[33] = (volatile float (*)[33])pbufB;

    const float sI = 0.5f, sF = 0.5f, sG = 1.0f, sO = 0.5f;

    u64 wif[H_], wgo[H_];
#pragma unroll
    for (int k = 0; k < H_; k++) {
        wif[k] = pk2(sI * W_hh[(0 * H_ + j) * H_ + k],
                     sF * W_hh[(1 * H_ + j) * H_ + k]);
        wgo[k] = pk2(sG * W_hh[(2 * H_ + j) * H_ + k],
                     sO * W_hh[(3 * H_ + j) * H_ + k]);
    }
    const u64 wih_if = pk2(sI * W_ih[0 * H_ + j], sF * W_ih[1 * H_ + j]);
    const u64 wih_go = pk2(sG * W_ih[2 * H_ + j], sO * W_ih[3 * H_ + j]);
    const u64 bs_if  = pk2(sI * (b_ih[0 * H_ + j] + b_hh[0 * H_ + j]),
                           sF * (b_ih[1 * H_ + j] + b_hh[1 * H_ + j]));
    const u64 bs_go  = pk2(sG * (b_ih[2 * H_ + j] + b_hh[2 * H_ + j]),
                           sO * (b_ih[3 * H_ + j] + b_hh[3 * H_ + j]));
    const float wout = W_out[j];
    const float bout = b_out[0];
    const u64 z2 = 0ull;

    const unsigned hA0 = (unsigned)__cvta_generic_to_shared(&hA[0][0]);
    const unsigned hA1 = hA0 + (unsigned)(H_ * sizeof(u64));
    const unsigned hB0 = (unsigned)__cvta_generic_to_shared(&hB[0][0]);
    const unsigned hB1 = hB0 + (unsigned)(H_ * sizeof(u64));

    float cA = 0.0f, cB = 0.0f;
    sts64(hA0 + j * 8, z2);
    sts64(hB0 + j * 8, z2);

    const float* xbA = x + (size_t)bA * T_;
    const float* xbB = x + (size_t)bB * T_;
    float* obA = out + (size_t)bA * T_;
    float* obB = out + (size_t)bB * T_;

    // ---- gate phase: returns packed preacts (no side effects) ----
    auto gates = [&](const float* __restrict__ xb, unsigned rd, int t,
                     u64& aif, u64& ago) {
        const int tc_ = (t < T_) ? t : (T_ - 1);
        const float xv = xb[tc_];
        const u64 xd = pk2(xv, xv);
        u64 a0 = fma2(xd, wih_if, bs_if);
        u64 g0 = fma2(xd, wih_go, bs_go);
        u64 a1 = z2, g1 = z2;
#pragma unroll
        for (int k = 0; k < H_; k += 2) {
            u64 p0, p1;
            lds2(p0, p1, rd + k * 8);
            a0 = fma2(p0, wif[k],     a0);
            g0 = fma2(p0, wgo[k],     g0);
            a1 = fma2(p1, wif[k + 1], a1);
            g1 = fma2(p1, wgo[k + 1], g1);
        }
        aif = add2(a0, a1);
        ago = add2(g0, g1);
    };

    // ---- tail phase: activations, c/h update, h store, pbuf write ----
    auto tail = [&](u64 aif, u64 ago, float& c, unsigned wr,
                    volatile float (*pv)[33], int tt) {
        float ai, af, ag, ao;
        upk2(aif, ai, af);
        upk2(ago, ag, ao);
        const float ti = tanhf_(ai);
        const float tf = tanhf_(af);
        const float g_ = tanhf_(ag);
        const float to = tanhf_(ao);
        const float i_ = fmaf(ti, 0.5f, 0.5f);
        const float f_ = fmaf(tf, 0.5f, 0.5f);
        const float o_ = fmaf(to, 0.5f, 0.5f);
        c = fmaf(f_, c, i_ * g_);
        const float h = o_ * tanhf_(c);
        sts64(wr, pk2(h, h));
        pv[tt][j] = h * wout;
    };

    // Prologue: A's gate phase for t=0.
    u64 aifA, agoA, aifB, agoB;
    gates(xbA, hA0, 0, aifA, agoA);

    for (int t0 = 0; t0 < T_; t0 += 32) {
#pragma unroll 2
        for (int tt = 0; tt < 32; ++tt) {
            const int t = t0 + tt;
            const unsigned rdA = (t & 1) ? hA1 : hA0;   // h(t) lives in parity t&1... 
            const unsigned wrA = (((t + 1) & 1) ? hA1 : hA0) + j * 8;
            const unsigned rdB = (t & 1) ? hB1 : hB0;
            const unsigned wrB = (((t + 1) & 1) ? hB1 : hB0) + j * 8;
            // Note: h(t) stored at parity (t&1) by tail(t-1); gates(t) reads it.
            // h(0) seeded at parity 0. tail(t) writes parity (t+1)&1. Consistent.

            // gatesB(t)  || tailA(t): independent -> ptxas interleaves.
            gates(xbB, rdB, t, aifB, agoB);
            tail(aifA, agoA, cA, wrA, pvA, tt);

            // gatesA(t+1) || tailB(t): gatesA reads hA written by tailA above
            // (same warp, LSU-ordered); tailB's MUFU ladder overlaps its FMAs.
            gates(xbA, (((t + 1) & 1) ? hA1 : hA0), t + 1, aifA, agoA);
            tail(aifB, agoB, cB, wrB, pvB, tt);
        }
        // Transposed reductions: lane j sums the 32 partials of timestep t0+j.
        float sA0 = 0.0f, sA1 = 0.0f, sB0 = 0.0f, sB1 = 0.0f;
#pragma unroll
        for (int k = 0; k < 32; k += 2) {
            sA0 += pvA[j][k];
            sB0 += pvB[j][k];
            sA1 += pvA[j][k + 1];
            sB1 += pvB[j][k + 1];
        }
        obA[t0 + j] = sA0 + sA1 + bout;
        obB[t0 + j] = sB0 + sB1 + bout;
    }
}

extern "C" void kernel_launch(void* const* d_in, const int* in_sizes, int n_in,
                              void* d_out, int out_size) {
    const float* x     = (const float*)d_in[0];
    const float* W_ih  = (const float*)d_in[1];
    const float* W_hh  = (const float*)d_in[2];
    const float* b_ih  = (const float*)d_in[3];
    const float* b_hh  = (const float*)d_in[4];
    const float* W_out = (const float*)d_in[5];
    const float* b_out = (const float*)d_in[6];
    float* out = (float*)d_out;

    lstm_kernel<<<B_ / 2, 32>>>(x, W_ih, W_hh, b_ih, b_hh, W_out, b_out, out);
}

// round 7
// speedup vs baseline: 1.1169x; 1.0625x over previous
#include <cuda_runtime.h>

// LSTM: B=1024, T=2048, H=32, I=1.
// One warp per batch element. Lane j owns hidden unit j.
// Gates packed (i,f),(g,o) in f32x2; h broadcast via duplicated smem pairs
// (double-buffered, converged warp -> no syncs).
// 4-way split accumulator chains (8 FMA2 deep) for ILP; two-phase tanh overlap.
// sigmoid(a)=0.5*tanh(a/2)+0.5 with pre-scaled weights; MUFU.TANH.

#define B_ 1024
#define T_ 2048
#define H_ 32

typedef unsigned long long u64;

static __device__ __forceinline__ u64 pk2(float lo, float hi) {
    u64 r;
    asm("mov.b64 %0, {%1, %2};" : "=l"(r) : "f"(lo), "f"(hi));
    return r;
}
static __device__ __forceinline__ void upk2(u64 v, float& lo, float& hi) {
    asm("mov.b64 {%0, %1}, %2;" : "=f"(lo), "=f"(hi) : "l"(v));
}
static __device__ __forceinline__ u64 fma2(u64 a, u64 b, u64 c) {
    u64 d;
    asm("fma.rn.f32x2 %0, %1, %2, %3;" : "=l"(d) : "l"(a), "l"(b), "l"(c));
    return d;
}
static __device__ __forceinline__ u64 add2(u64 a, u64 b) {
    u64 d;
    asm("add.rn.f32x2 %0, %1, %2;" : "=l"(d) : "l"(a), "l"(b));
    return d;
}
static __device__ __forceinline__ float tanhf_(float x) {
    float r; asm("tanh.approx.f32 %0, %1;" : "=f"(r) : "f"(x)); return r;
}
static __device__ __forceinline__ void lds2(u64& p0, u64& p1, unsigned addr) {
    asm volatile("ld.shared.v2.b64 {%0, %1}, [%2];"
                 : "=l"(p0), "=l"(p1) : "r"(addr));
}
static __device__ __forceinline__ void sts64(unsigned addr, u64 v) {
    asm volatile("st.shared.b64 [%0], %1;" :: "r"(addr), "l"(v));
}

__global__ void __launch_bounds__(32)
lstm_kernel(const float* __restrict__ x,
            const float* __restrict__ W_ih,
            const float* __restrict__ W_hh,
            const float* __restrict__ b_ih,
            const float* __restrict__ b_hh,
            const float* __restrict__ W_out,
            const float* __restrict__ b_out,
            float* __restrict__ out) {
    const int j = threadIdx.x;   // hidden unit
    const int b = blockIdx.x;    // batch element

    __shared__ u64 hbuf[2][H_];               // duplicated (h,h) pairs, double-buffered
    __shared__ float pbuf[32][33];            // per-step output partials (padded)
    volatile float (*pv)[33] = (volatile float (*)[33])pbuf;

    const float sI = 0.5f, sF = 0.5f, sG = 1.0f, sO = 0.5f;

    u64 wif[H_], wgo[H_];
#pragma unroll
    for (int k = 0; k < H_; k++) {
        wif[k] = pk2(sI * W_hh[(0 * H_ + j) * H_ + k],
                     sF * W_hh[(1 * H_ + j) * H_ + k]);
        wgo[k] = pk2(sG * W_hh[(2 * H_ + j) * H_ + k],
                     sO * W_hh[(3 * H_ + j) * H_ + k]);
    }
    const u64 wih_if = pk2(sI * W_ih[0 * H_ + j], sF * W_ih[1 * H_ + j]);
    const u64 wih_go = pk2(sG * W_ih[2 * H_ + j], sO * W_ih[3 * H_ + j]);
    const u64 bs_if  = pk2(sI * (b_ih[0 * H_ + j] + b_hh[0 * H_ + j]),
                           sF * (b_ih[1 * H_ + j] + b_hh[1 * H_ + j]));
    const u64 bs_go  = pk2(sG * (b_ih[2 * H_ + j] + b_hh[2 * H_ + j]),
                           sO * (b_ih[3 * H_ + j] + b_hh[3 * H_ + j]));
    const float wout = W_out[j];
    const float bout = b_out[0];
    const u64 z2 = 0ull;

    const unsigned hb0 = (unsigned)__cvta_generic_to_shared(&hbuf[0][0]);
    const unsigned hb1 = hb0 + (unsigned)(H_ * sizeof(u64));
    const unsigned st0 = hb0 + j * 8;
    const unsigned st1 = hb1 + j * 8;

    float c = 0.0f;
    sts64(st0, z2);    // h_{-1} = 0

    const float* xb = x + (size_t)b * T_;
    float* ob = out + (size_t)b * T_;
    float xc = xb[0];

    for (int t0 = 0; t0 < T_; t0 += 32) {
#pragma unroll 4
        for (int tt = 0; tt < 32; ++tt) {
            const int t = t0 + tt;
            const int tn = (t + 1 < T_) ? (t + 1) : (T_ - 1);
            const float xn = xb[tn];   // prefetch next x

            const unsigned rdaddr = (t & 1) ? hb1 : hb0;
            const unsigned wraddr = (t & 1) ? st0 : st1;

            const u64 xd = pk2(xc, xc);

            // ---- Phase 1: (i,f) over all 32 h; 4 independent chains of 8 ----
            u64 hr[H_];
            u64 a0 = fma2(xd, wih_if, bs_if);
            u64 a1 = z2, a2 = z2, a3 = z2;
#pragma unroll
            for (int k = 0; k < H_; k += 4) {
                u64 p0, p1, p2, p3;
                lds2(p0, p1, rdaddr + k * 8);
                lds2(p2, p3, rdaddr + k * 8 + 16);
                hr[k] = p0; hr[k + 1] = p1; hr[k + 2] = p2; hr[k + 3] = p3;
                a0 = fma2(p0, wif[k],     a0);
                a1 = fma2(p1, wif[k + 1], a1);
                a2 = fma2(p2, wif[k + 2], a2);
                a3 = fma2(p3, wif[k + 3], a3);
            }
            const u64 aif = add2(add2(a0, a1), add2(a2, a3));
            float ai, af;
            upk2(aif, ai, af);
            const float ti = tanhf_(ai);   // MUFU overlaps phase-2 FMA issue
            const float tf = tanhf_(af);

            // ---- Phase 2: (g,o) from stashed h; 4 chains of 8 ----
            u64 g0 = fma2(xd, wih_go, bs_go);
            u64 g1 = z2, g2 = z2, g3 = z2;
#pragma unroll
            for (int k = 0; k < H_; k += 4) {
                g0 = fma2(hr[k],     wgo[k],     g0);
                g1 = fma2(hr[k + 1], wgo[k + 1], g1);
                g2 = fma2(hr[k + 2], wgo[k + 2], g2);
                g3 = fma2(hr[k + 3], wgo[k + 3], g3);
            }
            const u64 ago = add2(add2(g0, g1), add2(g2, g3));
            float ag, ao;
            upk2(ago, ag, ao);
            const float g_ = tanhf_(ag);
            const float to = tanhf_(ao);

            const float i_ = fmaf(ti, 0.5f, 0.5f);
            const float f_ = fmaf(tf, 0.5f, 0.5f);
            const float o_ = fmaf(to, 0.5f, 0.5f);

            c = fmaf(f_, c, i_ * g_);
            const float h = o_ * tanhf_(c);

            sts64(wraddr, pk2(h, h));      // broadcast h (converged warp)
            pv[tt][j] = h * wout;
            xc = xn;
        }
        // Transposed reduction: lane j sums the 32 partials of timestep t0+j.
        float s0 = 0.0f, s1 = 0.0f, s2 = 0.0f, s3 = 0.0f;
#pragma unroll
        for (int k = 0; k < 32; k += 4) {
            s0 += pv[j][k];
            s1 += pv[j][k + 1];
            s2 += pv[j][k + 2];
            s3 += pv[j][k + 3];
        }
        ob[t0 + j] = (s0 + s1) + (s2 + s3) + bout;
    }
}

extern "C" void kernel_launch(void* const* d_in, const int* in_sizes, int n_in,
                              void* d_out, int out_size) {
    const float* x     = (const float*)d_in[0];
    const float* W_ih  = (const float*)d_in[1];
    const float* W_hh  = (const float*)d_in[2];
    const float* b_ih  = (const float*)d_in[3];
    const float* b_hh  = (const float*)d_in[4];
    const float* W_out = (const float*)d_in[5];
    const float* b_out = (const float*)d_in[6];
    float* out = (float*)d_out;

    lstm_kernel<<<B_, 32>>>(x, W_ih, W_hh, b_ih, b_hh, W_out, b_out, out);
}

// round 8
// speedup vs baseline: 1.1208x; 1.0035x over previous
#include <cuda_runtime.h>

// LSTM: B=1024, T=2048, H=32, I=1.
// One warp per batch element. Lane j owns hidden unit j.
// Single fused k-loop with manual 1-group LDS lookahead; 8 accumulator chains.
// Gates packed (i,f),(g,o) in f32x2; h broadcast via duplicated smem pairs
// (double-buffered, converged warp -> no syncs).
// sigmoid(a)=0.5*tanh(a/2)+0.5 with pre-scaled weights; MUFU.TANH.

#define B_ 1024
#define T_ 2048
#define H_ 32

typedef unsigned long long u64;

static __device__ __forceinline__ u64 pk2(float lo, float hi) {
    u64 r;
    asm("mov.b64 %0, {%1, %2};" : "=l"(r) : "f"(lo), "f"(hi));
    return r;
}
static __device__ __forceinline__ void upk2(u64 v, float& lo, float& hi) {
    asm("mov.b64 {%0, %1}, %2;" : "=f"(lo), "=f"(hi) : "l"(v));
}
static __device__ __forceinline__ u64 fma2(u64 a, u64 b, u64 c) {
    u64 d;
    asm("fma.rn.f32x2 %0, %1, %2, %3;" : "=l"(d) : "l"(a), "l"(b), "l"(c));
    return d;
}
static __device__ __forceinline__ u64 add2(u64 a, u64 b) {
    u64 d;
    asm("add.rn.f32x2 %0, %1, %2;" : "=l"(d) : "l"(a), "l"(b));
    return d;
}
static __device__ __forceinline__ float tanhf_(float x) {
    float r; asm("tanh.approx.f32 %0, %1;" : "=f"(r) : "f"(x)); return r;
}
static __device__ __forceinline__ void lds2(u64& p0, u64& p1, unsigned addr) {
    asm volatile("ld.shared.v2.b64 {%0, %1}, [%2];"
                 : "=l"(p0), "=l"(p1) : "r"(addr));
}
static __device__ __forceinline__ void sts64(unsigned addr, u64 v) {
    asm volatile("st.shared.b64 [%0], %1;" :: "r"(addr), "l"(v));
}

__global__ void __launch_bounds__(32)
lstm_kernel(const float* __restrict__ x,
            const float* __restrict__ W_ih,
            const float* __restrict__ W_hh,
            const float* __restrict__ b_ih,
            const float* __restrict__ b_hh,
            const float* __restrict__ W_out,
            const float* __restrict__ b_out,
            float* __restrict__ out) {
    const int j = threadIdx.x;   // hidden unit
    const int b = blockIdx.x;    // batch element

    __shared__ u64 hbuf[2][H_];               // duplicated (h,h) pairs, double-buffered
    __shared__ float pbuf[32][33];            // per-step output partials (padded)
    volatile float (*pv)[33] = (volatile float (*)[33])pbuf;

    const float sI = 0.5f, sF = 0.5f, sG = 1.0f, sO = 0.5f;

    u64 wif[H_], wgo[H_];
#pragma unroll
    for (int k = 0; k < H_; k++) {
        wif[k] = pk2(sI * W_hh[(0 * H_ + j) * H_ + k],
                     sF * W_hh[(1 * H_ + j) * H_ + k]);
        wgo[k] = pk2(sG * W_hh[(2 * H_ + j) * H_ + k],
                     sO * W_hh[(3 * H_ + j) * H_ + k]);
    }
    const u64 wih_if = pk2(sI * W_ih[0 * H_ + j], sF * W_ih[1 * H_ + j]);
    const u64 wih_go = pk2(sG * W_ih[2 * H_ + j], sO * W_ih[3 * H_ + j]);
    const u64 bs_if  = pk2(sI * (b_ih[0 * H_ + j] + b_hh[0 * H_ + j]),
                           sF * (b_ih[1 * H_ + j] + b_hh[1 * H_ + j]));
    const u64 bs_go  = pk2(sG * (b_ih[2 * H_ + j] + b_hh[2 * H_ + j]),
                           sO * (b_ih[3 * H_ + j] + b_hh[3 * H_ + j]));
    const float wout = W_out[j];
    const float bout = b_out[0];
    const u64 z2 = 0ull;

    const unsigned hb0 = (unsigned)__cvta_generic_to_shared(&hbuf[0][0]);
    const unsigned hb1 = hb0 + (unsigned)(H_ * sizeof(u64));
    const unsigned st0 = hb0 + j * 8;
    const unsigned st1 = hb1 + j * 8;

    float c = 0.0f;
    sts64(st0, z2);    // h_{-1} = 0

    const float* xb = x + (size_t)b * T_;
    float* ob = out + (size_t)b * T_;
    float xc = xb[0];

    for (int t0 = 0; t0 < T_; t0 += 32) {
#pragma unroll 4
        for (int tt = 0; tt < 32; ++tt) {
            const int t = t0 + tt;
            const int tn = (t + 1 < T_) ? (t + 1) : (T_ - 1);
            const float xn = xb[tn];   // prefetch next x

            const unsigned rdaddr = (t & 1) ? hb1 : hb0;
            const unsigned wraddr = (t & 1) ? st0 : st1;

            const u64 xd = pk2(xc, xc);

            // 8 independent accumulator chains, single fused loop,
            // manual 1-group (k+4) load lookahead.
            u64 a0 = fma2(xd, wih_if, bs_if);
            u64 g0 = fma2(xd, wih_go, bs_go);
            u64 a1 = z2, a2 = z2, a3 = z2;
            u64 g1 = z2, g2 = z2, g3 = z2;

            u64 p0, p1, p2, p3;
            lds2(p0, p1, rdaddr);
            lds2(p2, p3, rdaddr + 16);
#pragma unroll
            for (int k = 0; k < H_ - 4; k += 4) {
                u64 q0, q1, q2, q3;
                lds2(q0, q1, rdaddr + (k + 4) * 8);        // next group, issued early
                lds2(q2, q3, rdaddr + (k + 4) * 8 + 16);
                a0 = fma2(p0, wif[k],     a0);
                g0 = fma2(p0, wgo[k],     g0);
                a1 = fma2(p1, wif[k + 1], a1);
                g1 = fma2(p1, wgo[k + 1], g1);
                a2 = fma2(p2, wif[k + 2], a2);
                g2 = fma2(p2, wgo[k + 2], g2);
                a3 = fma2(p3, wif[k + 3], a3);
                g3 = fma2(p3, wgo[k + 3], g3);
                p0 = q0; p1 = q1; p2 = q2; p3 = q3;
            }
            {
                const int k = H_ - 4;
                a0 = fma2(p0, wif[k],     a0);
                g0 = fma2(p0, wgo[k],     g0);
                a1 = fma2(p1, wif[k + 1], a1);
                g1 = fma2(p1, wgo[k + 1], g1);
                a2 = fma2(p2, wif[k + 2], a2);
                g2 = fma2(p2, wgo[k + 2], g2);
                a3 = fma2(p3, wif[k + 3], a3);
                g3 = fma2(p3, wgo[k + 3], g3);
            }
            const u64 aif = add2(add2(a0, a1), add2(a2, a3));
            const u64 ago = add2(add2(g0, g1), add2(g2, g3));

            float ai, af, ag, ao;
            upk2(aif, ai, af);
            upk2(ago, ag, ao);
            const float ti = tanhf_(ai);
            const float tf = tanhf_(af);
            const float g_ = tanhf_(ag);
            const float to = tanhf_(ao);

            const float i_ = fmaf(ti, 0.5f, 0.5f);
            const float f_ = fmaf(tf, 0.5f, 0.5f);
            const float o_ = fmaf(to, 0.5f, 0.5f);

            c = fmaf(f_, c, i_ * g_);
            const float h = o_ * tanhf_(c);

            sts64(wraddr, pk2(h, h));      // broadcast h (converged warp)
            pv[tt][j] = h * wout;
            xc = xn;
        }
        // Transposed reduction: lane j sums the 32 partials of timestep t0+j.
        float s0 = 0.0f, s1 = 0.0f, s2 = 0.0f, s3 = 0.0f;
#pragma unroll
        for (int k = 0; k < 32; k += 4) {
            s0 += pv[j][k];
            s1 += pv[j][k + 1];
            s2 += pv[j][k + 2];
            s3 += pv[j][k + 3];
        }
        ob[t0 + j] = (s0 + s1) + (s2 + s3) + bout;
    }
}

extern "C" void kernel_launch(void* const* d_in, const int* in_sizes, int n_in,
                              void* d_out, int out_size) {
    const float* x     = (const float*)d_in[0];
    const float* W_ih  = (const float*)d_in[1];
    const float* W_hh  = (const float*)d_in[2];
    const float* b_ih  = (const float*)d_in[3];
    const float* b_hh  = (const float*)d_in[4];
    const float* W_out = (const float*)d_in[5];
    const float* b_out = (const float*)d_in[6];
    float* out = (float*)d_out;

    lstm_kernel<<<B_, 32>>>(x, W_ih, W_hh, b_ih, b_hh, W_out, b_out, out);
}